// round 10
// baseline (speedup 1.0000x reference)
#include <cuda_runtime.h>
#include <cuda_fp16.h>
#include <cstdint>

#define B_DIM 4096
#define SPLIT 32
#define D_DIM 256
#define UNITS 256

#define MTILE 128
#define NTILE 128
#define KC 64
#define NSTAGE (D_DIM / KC)   // 4

// ---------------- smem layout ----------------
#define APITCH 144                      // bytes per 64-elem fp16 row (128B data + 16B pad, ldsm conflict-free)
#define ABYTES (128 * APITCH)           // 18432 per buffer (2 buffers)
#define BBYTES (128 * APITCH)           // 18432 per buffer (3 buffers)
#define SM_A 0                          // 2 buffers -> 36864
#define SM_B 36864                      // 3 buffers -> 55296
#define SM_TOTAL (36864 + 55296)        // 92160 -> 2 CTAs/SM

// pre-converted W: fp16 bits, layout [s][n][k] (k contiguous)
__device__ __align__(16) unsigned short g_Wh[SPLIT * UNITS * D_DIM];

// ---------------- helpers ----------------
__device__ __forceinline__ uint32_t smem_u32(const void* p) {
    uint32_t a;
    asm("{ .reg .u64 t; cvta.to.shared.u64 t, %1; cvt.u32.u64 %0, t; }" : "=r"(a) : "l"(p));
    return a;
}

#define STS128(addr, v) \
    asm volatile("st.shared.v4.b32 [%0], {%1,%2,%3,%4};" :: "r"(addr), "r"((v).x), "r"((v).y), "r"((v).z), "r"((v).w) : "memory")

__device__ __forceinline__ void cp16(uint32_t dst, const void* src) {
    asm volatile("cp.async.cg.shared.global [%0], [%1], 16;"
                 :: "r"(dst), "l"((unsigned long long)__cvta_generic_to_global(src)) : "memory");
}
#define CP_COMMIT() asm volatile("cp.async.commit_group;" ::: "memory")
#define CP_WAIT1()  asm volatile("cp.async.wait_group 1;" ::: "memory")

__device__ __forceinline__ void ldsm4(uint32_t* r, uint32_t addr) {
    asm volatile("ldmatrix.sync.aligned.m8n8.x4.shared.b16 {%0,%1,%2,%3}, [%4];"
                 : "=r"(r[0]), "=r"(r[1]), "=r"(r[2]), "=r"(r[3]) : "r"(addr));
}

__device__ __forceinline__ void mma_f16(float* d, const uint32_t* a, const uint32_t* b) {
    asm volatile("mma.sync.aligned.m16n8k16.row.col.f32.f16.f16.f32 "
                 "{%0,%1,%2,%3}, {%4,%5,%6,%7}, {%8,%9}, {%0,%1,%2,%3};"
                 : "+f"(d[0]), "+f"(d[1]), "+f"(d[2]), "+f"(d[3])
                 : "r"(a[0]), "r"(a[1]), "r"(a[2]), "r"(a[3]), "r"(b[0]), "r"(b[1]));
}

// convert 8 fp32 -> 4 packed fp16x2 words
__device__ __forceinline__ void cvt8(const float4 a, const float4 c, uint32_t* h) {
    asm("cvt.rn.f16x2.f32 %0, %1, %2;" : "=r"(h[0]) : "f"(a.y), "f"(a.x));
    asm("cvt.rn.f16x2.f32 %0, %1, %2;" : "=r"(h[1]) : "f"(a.w), "f"(a.z));
    asm("cvt.rn.f16x2.f32 %0, %1, %2;" : "=r"(h[2]) : "f"(c.y), "f"(c.x));
    asm("cvt.rn.f16x2.f32 %0, %1, %2;" : "=r"(h[3]) : "f"(c.w), "f"(c.z));
}

// load 32 floats (8 float4) at src, convert to 16 packed fp16x2 words
__device__ __forceinline__ void load_cvt32(const float* src, uint32_t* xh) {
#pragma unroll
    for (int p = 0; p < 4; p++) {
        float4 a = __ldg((const float4*)src + 2 * p);
        float4 c = __ldg((const float4*)src + 2 * p + 1);
        cvt8(a, c, xh + 4 * p);
    }
}

// ---------------- prep kernel: W[s][k][n] fp32 -> g_Wh [s][n][k] fp16 ----------------
__global__ void prep_w_kernel(const float* __restrict__ W) {
    __shared__ float tile[32][33];
    int s = blockIdx.z;
    int kb = blockIdx.y * 32;
    int nb = blockIdx.x * 32;
    int tx = threadIdx.x, ty = threadIdx.y;
    const float* Ws = W + (size_t)s * D_DIM * UNITS;
#pragma unroll
    for (int i = 0; i < 4; i++) {
        int k = kb + ty + 8 * i;
        tile[ty + 8 * i][tx] = Ws[(size_t)k * UNITS + nb + tx];
    }
    __syncthreads();
#pragma unroll
    for (int i = 0; i < 4; i++) {
        int n = nb + ty + 8 * i;
        int k = kb + tx;
        g_Wh[((size_t)s * UNITS + n) * D_DIM + k] =
            __half_as_ushort(__float2half_rn(tile[tx][ty + 8 * i]));
    }
}

// ---------------- main GEMM (fp16 HMMA, KC=64, 4 chunks, 2 CTAs/SM) ----------------
__global__ void __launch_bounds__(256, 2) lc_hmma_kernel(
    const float* __restrict__ x, const float* __restrict__ bias, float* __restrict__ out) {
    extern __shared__ char smem[];
    uint32_t sb = smem_u32(smem);
    int tid = threadIdx.x;
    int wid = tid >> 5, lid = tid & 31;
    int mb = blockIdx.x >> 1;       // batch tile
    int nb = blockIdx.x & 1;        // n half (adjacent -> shared x slice hits L2)
    int s  = blockIdx.y;            // split
    int wm = wid >> 2;              // 0..1 : m half (64 rows)
    int wn = wid & 3;               // 0..3 : n quarter (32 cols)

    float acc[4][4][4];
#pragma unroll
    for (int i = 0; i < 4; i++)
#pragma unroll
        for (int j = 0; j < 4; j++)
#pragma unroll
            for (int v = 0; v < 4; v++) acc[i][j][v] = 0.f;

    // A staging: thread -> (row tid/2, 32-float half tid%2)
    int arow = tid >> 1, ahalf = tid & 1;
    const float* xbase = x + (((size_t)(mb * MTILE + arow) * SPLIT + s) * D_DIM) + ahalf * 32;
    uint32_t asts = sb + SM_A + (uint32_t)(arow * APITCH + ahalf * 64);

    // B staging: thread -> (n-row tid/2, 32-elem half), 4 cp16 per chunk
    const unsigned short* whsrc = g_Wh + ((size_t)s * UNITS + nb * NTILE + arow) * D_DIM + ahalf * 32;
    uint32_t bsts = sb + SM_B + (uint32_t)(arow * APITCH + ahalf * 64);

    // ldmatrix lane offsets
    uint32_t a_off = (uint32_t)((wm * 64 + (lid & 7) + ((lid >> 3) & 1) * 8) * APITCH + (lid >> 4) * 16);
    uint32_t b_off = (uint32_t)((wn * 32 + (lid & 7) + ((lid >> 4) & 1) * 8) * APITCH + ((lid >> 3) & 1) * 16);

    uint32_t xh[16];   // converted fp16 A words for next chunk (carried)

    // ---- prologue ----
    // A chunk 0: LDG+cvt, STS -> buf 0
    load_cvt32(xbase, xh);
#pragma unroll
    for (int p = 0; p < 4; p++) STS128(asts + p * 16, *(uint4*)(xh + 4 * p));
    // B chunk 0 -> buf 0 (group 0)
#pragma unroll
    for (int c = 0; c < 4; c++) cp16(bsts + c * 16, whsrc + c * 8);
    CP_COMMIT();
    // B chunk 1 -> buf 1 (group 1)
#pragma unroll
    for (int c = 0; c < 4; c++) cp16(bsts + BBYTES + c * 16, whsrc + KC + c * 8);
    CP_COMMIT();
    // A chunk 1: LDG+cvt (carried)
    load_cvt32(xbase + KC, xh);
    CP_WAIT1();           // chunk 0 B done
    __syncthreads();

    // ---- main loop over 4 K-chunks ----
#pragma unroll 1
    for (int kc = 0; kc < NSTAGE; kc++) {
        // B cp.async for chunk kc+2
        if (kc + 2 < NSTAGE) {
            uint32_t bd = bsts + (uint32_t)(((kc + 2) % 3) * BBYTES);
            const unsigned short* wh = whsrc + (kc + 2) * KC;
#pragma unroll
            for (int c = 0; c < 4; c++) cp16(bd + c * 16, wh + c * 8);
        }
        CP_COMMIT();

        // A: STS chunk kc+1 (converted words carried from last iter)
        if (kc + 1 < NSTAGE) {
            uint32_t ad = asts + (uint32_t)(((kc + 1) & 1) * ABYTES);
#pragma unroll
            for (int p = 0; p < 4; p++) STS128(ad + p * 16, *(uint4*)(xh + 4 * p));
        }
        // A: LDG+cvt chunk kc+2 into carried regs
        if (kc + 2 < NSTAGE) {
            load_cvt32(xbase + (kc + 2) * KC, xh);
        }

        // ---- compute chunk kc: 4 k16 steps ----
        uint32_t abase = sb + SM_A + (uint32_t)((kc & 1) * ABYTES) + a_off;
        uint32_t bbase = sb + SM_B + (uint32_t)((kc % 3) * BBYTES) + b_off;
#pragma unroll
        for (int ks = 0; ks < 4; ks++) {
            uint32_t ab = abase + ks * 32;
            uint32_t bb = bbase + ks * 32;
            uint32_t ah[16], bh[8];
#pragma unroll
            for (int mf = 0; mf < 4; mf++) ldsm4(&ah[4 * mf], ab + mf * 16 * APITCH);
#pragma unroll
            for (int p = 0; p < 2; p++) ldsm4(&bh[4 * p], bb + p * 16 * APITCH);
#pragma unroll
            for (int mf = 0; mf < 4; mf++)
#pragma unroll
                for (int nf = 0; nf < 4; nf++) mma_f16(acc[mf][nf], &ah[4 * mf], &bh[2 * nf]);
        }

        if (kc < NSTAGE - 1) {
            CP_WAIT1();
            __syncthreads();
        }
    }

    // ---- epilogue: bias + relu + store ----
    const float* brow = bias + s * UNITS + nb * NTILE;
#pragma unroll
    for (int mf = 0; mf < 4; mf++) {
        int r0 = mb * MTILE + wm * 64 + mf * 16 + (lid >> 2);
        float* o0 = out + ((size_t)r0 * SPLIT + s) * UNITS + nb * NTILE;
        float* o1 = o0 + (size_t)8 * SPLIT * UNITS;
#pragma unroll
        for (int nf = 0; nf < 4; nf++) {
            int c = wn * 32 + nf * 8 + 2 * (lid & 3);
            float2 bv = *(const float2*)(brow + c);
            float2 v0, v1;
            v0.x = fmaxf(acc[mf][nf][0] + bv.x, 0.f);
            v0.y = fmaxf(acc[mf][nf][1] + bv.y, 0.f);
            v1.x = fmaxf(acc[mf][nf][2] + bv.x, 0.f);
            v1.y = fmaxf(acc[mf][nf][3] + bv.y, 0.f);
            *(float2*)(o0 + c) = v0;
            *(float2*)(o1 + c) = v1;
        }
    }
}

// ---------------- launch ----------------
extern "C" void kernel_launch(void* const* d_in, const int* in_sizes, int n_in,
                              void* d_out, int out_size) {
    const float* x = (const float*)d_in[0];
    const float* W = (const float*)d_in[1];
    const float* b = (const float*)d_in[2];
    float* out = (float*)d_out;

    prep_w_kernel<<<dim3(8, 8, 32), dim3(32, 8)>>>(W);

    cudaFuncSetAttribute(lc_hmma_kernel, cudaFuncAttributeMaxDynamicSharedMemorySize, SM_TOTAL);
    lc_hmma_kernel<<<dim3((B_DIM / MTILE) * 2, SPLIT), 256, SM_TOTAL>>>(x, b, out);
}